// round 2
// baseline (speedup 1.0000x reference)
#include <cuda_runtime.h>

#define B_  2
#define C_  512
#define N_  2048
#define H_  8
#define DK_ 64
#define BH_ (B_*H_)

#define QT  16
#define KC  256
#define KPAD 65
#define VPAD 66

// Scratch (allocation-free rule: __device__ globals)
__device__ float g_q[BH_*N_*DK_];
__device__ float g_k[BH_*N_*DK_];
__device__ float g_v[BH_*N_*DK_];
__device__ float g_o[BH_*N_*DK_];

// ---------------------------------------------------------------------------
// Kernel 1: fused QKV projection.  Y[b,n,o] = sum_c x[b,c,n]*Wcat[o,c] + bcat[o]
// Tiled SGEMM: 64(n) x 64(o) x 16(c) tiles, 256 threads, 4x4 microtile.
// Writes directly into per-head layout g_{q,k,v}[((b*H+h)*N + n)*64 + d].
// ---------------------------------------------------------------------------
__global__ __launch_bounds__(256) void qkv_kernel(
    const float* __restrict__ x,
    const float* __restrict__ Wq, const float* __restrict__ bq,
    const float* __restrict__ Wk, const float* __restrict__ bk,
    const float* __restrict__ Wv, const float* __restrict__ bv)
{
    __shared__ float As[16][64];   // [c][n]
    __shared__ float Bs[16][65];   // [c][o]  (pad 65: conflict-free stores/loads)

    const int tid = threadIdx.x;
    const int ot  = blockIdx.x;          // 0..23  (o tiles of 64 over 1536)
    const int nt  = blockIdx.y;          // 0..31
    const int b   = blockIdx.z;

    const int o0    = ot * 64;
    const int mat   = o0 / 512;          // 0=Q 1=K 2=V
    const int orow0 = o0 % 512;
    const float* W    = (mat == 0) ? Wq : (mat == 1) ? Wk : Wv;
    const float* bias = (mat == 0) ? bq : (mat == 1) ? bk : bv;
    float*       dst  = (mat == 0) ? g_q : (mat == 1) ? g_k : g_v;
    const int n0 = nt * 64;

    const int tn = tid >> 4;   // 0..15 (n group)
    const int to = tid & 15;   // 0..15 (o group)

    float acc[4][4];
    #pragma unroll
    for (int i = 0; i < 4; i++)
        #pragma unroll
        for (int j = 0; j < 4; j++) acc[i][j] = 0.f;

    for (int kt = 0; kt < 32; kt++) {
        const int c0 = kt * 16;
        #pragma unroll
        for (int t = 0; t < 4; t++) {
            int idx = tid + t * 256;
            int kk = idx >> 6, ni = idx & 63;
            As[kk][ni] = x[(b * C_ + c0 + kk) * N_ + n0 + ni];
        }
        #pragma unroll
        for (int t = 0; t < 4; t++) {
            int idx = tid + t * 256;
            int kk = idx & 15, oi = idx >> 4;
            Bs[kk][oi] = W[(orow0 + oi) * C_ + c0 + kk];
        }
        __syncthreads();
        #pragma unroll
        for (int kk = 0; kk < 16; kk++) {
            float a[4], bb[4];
            #pragma unroll
            for (int i = 0; i < 4; i++) a[i]  = As[kk][tn + 16 * i];
            #pragma unroll
            for (int j = 0; j < 4; j++) bb[j] = Bs[kk][to + 16 * j];
            #pragma unroll
            for (int i = 0; i < 4; i++)
                #pragma unroll
                for (int j = 0; j < 4; j++)
                    acc[i][j] = fmaf(a[i], bb[j], acc[i][j]);
        }
        __syncthreads();
    }

    #pragma unroll
    for (int j = 0; j < 4; j++) {
        int o = orow0 + to + 16 * j;
        float bval = bias[o];
        int h = o >> 6, d = o & 63;
        #pragma unroll
        for (int i = 0; i < 4; i++) {
            int n = n0 + tn + 16 * i;
            dst[((b * H_ + h) * N_ + n) * DK_ + d] = acc[i][j] + bval;
        }
    }
}

// ---------------------------------------------------------------------------
// Kernel 2: fused attention with exact 1.5-entmax (bisection for tau).
// One CTA per (bh, 16-query tile).  512 threads = 16 warps; warp w owns row w.
//   Phase 1: z = (q.k / sqrt(64)) / 2 into SMEM (16 x 2048), K staged in chunks
//   Phase 2: per-warp: z row into registers, warp max, 26 bisection iters,
//            write p = clip(z - tau)^2 back in place
//   Phase 3: o = p @ V with V staged in SMEM chunks, broadcast p reads
// ---------------------------------------------------------------------------
__global__ __launch_bounds__(512, 1) void attn_kernel()
{
    extern __shared__ float smem[];
    float* Es  = smem;               // QT * N_          (131072 B)
    float* Qs  = Es + QT * N_;       // QT * 64          (4096 B)
    float* KVs = Qs + QT * DK_;      // KC * VPAD        (67584 B)

    const int tid = threadIdx.x;
    const int bh  = blockIdx.y;
    const int q0  = blockIdx.x * QT;

    const float* qptr = g_q + (bh * N_ + q0) * DK_;
    const float* kptr = g_k + bh * N_ * DK_;
    const float* vptr = g_v + bh * N_ * DK_;

    // load Q tile (row-major [qi][d], contiguous)
    #pragma unroll
    for (int t = 0; t < 2; t++) {
        int idx = tid + t * 512;
        Qs[idx] = qptr[idx];
    }
    __syncthreads();

    // ---- Phase 1: energies -> Es (pre-scaled by 1/16 = (1/sqrt(64))/2) ----
    const int qg = tid >> 6;   // 0..7  (2 q rows each)
    const int kg = tid & 63;   // 0..63 (4 k cols each, strided by 64)
    const float scale = 1.f / 16.f;

    for (int kc = 0; kc < N_ / KC; kc++) {
        #pragma unroll
        for (int t = 0; t < (KC * DK_) / 512; t++) {
            int idx = tid + t * 512;
            int r = idx >> 6, cl = idx & 63;
            KVs[r * KPAD + cl] = kptr[(kc * KC + r) * DK_ + cl];
        }
        __syncthreads();

        float acc[2][4];
        #pragma unroll
        for (int ii = 0; ii < 2; ii++)
            #pragma unroll
            for (int jj = 0; jj < 4; jj++) acc[ii][jj] = 0.f;

        #pragma unroll 16
        for (int d = 0; d < 64; d++) {
            float a0 = Qs[(2 * qg)     * 64 + d];
            float a1 = Qs[(2 * qg + 1) * 64 + d];
            #pragma unroll
            for (int jj = 0; jj < 4; jj++) {
                float bv = KVs[(kg + 64 * jj) * KPAD + d];
                acc[0][jj] = fmaf(a0, bv, acc[0][jj]);
                acc[1][jj] = fmaf(a1, bv, acc[1][jj]);
            }
        }
        #pragma unroll
        for (int ii = 0; ii < 2; ii++)
            #pragma unroll
            for (int jj = 0; jj < 4; jj++)
                Es[(2 * qg + ii) * N_ + kc * KC + kg + 64 * jj] = acc[ii][jj] * scale;
        __syncthreads();
    }

    // ---- Phase 2: entmax15 per row (warp w -> row w), tau by bisection ----
    const int w = tid >> 5, l = tid & 31;
    float* erow = Es + w * N_;

    float z[64];
    #pragma unroll
    for (int j = 0; j < 64; j++) z[j] = erow[l + 32 * j];

    float m = -1e30f;
    #pragma unroll
    for (int j = 0; j < 64; j++) m = fmaxf(m, z[j]);
    #pragma unroll
    for (int off = 16; off; off >>= 1)
        m = fmaxf(m, __shfl_xor_sync(0xffffffffu, m, off));
    #pragma unroll
    for (int j = 0; j < 64; j++) z[j] -= m;

    // f(tau) = sum clip(z - tau)^2 is decreasing; tau* in [-1, 0]
    float lo = -1.f, hi = 0.f;
    for (int it = 0; it < 26; it++) {
        float mid = 0.5f * (lo + hi);
        float s = 0.f;
        #pragma unroll
        for (int j = 0; j < 64; j++) {
            float t = fmaxf(z[j] - mid, 0.f);
            s = fmaf(t, t, s);
        }
        #pragma unroll
        for (int off = 16; off; off >>= 1)
            s += __shfl_xor_sync(0xffffffffu, s, off);
        bool ge = (s >= 1.f);
        lo = ge ? mid : lo;
        hi = ge ? hi : mid;
    }
    float tau = 0.5f * (lo + hi);
    #pragma unroll
    for (int j = 0; j < 64; j++) {
        float t = fmaxf(z[j] - tau, 0.f);
        erow[l + 32 * j] = t * t;   // Es now holds p
    }
    __syncthreads();

    // ---- Phase 3: o = p @ V, V staged in SMEM, broadcast p ----
    float2 acc2 = make_float2(0.f, 0.f);
    for (int vc = 0; vc < N_ / KC; vc++) {
        if (vc > 0) __syncthreads();   // all warps done with previous V chunk
        #pragma unroll
        for (int t = 0; t < (KC * DK_) / 512; t++) {
            int idx = tid + t * 512;
            int r = idx >> 6, cl = idx & 63;
            KVs[r * VPAD + cl] = vptr[(vc * KC + r) * DK_ + cl];
        }
        __syncthreads();

        const float* prow = erow + vc * KC;
        #pragma unroll 8
        for (int k = 0; k < KC; k++) {
            float p = prow[k];                 // broadcast LDS, warp-uniform
            if (p != 0.f) {                    // entmax sparsity: skip zeros
                float2 v = *reinterpret_cast<const float2*>(&KVs[k * VPAD + 2 * l]);
                acc2.x = fmaf(p, v.x, acc2.x);
                acc2.y = fmaf(p, v.y, acc2.y);
            }
        }
    }

    float* orow = g_o + (bh * N_ + q0 + w) * DK_;
    reinterpret_cast<float2*>(orow)[l] = acc2;
}

// ---------------------------------------------------------------------------
// Kernel 3: residual + LayerNorm (unbiased std, eps added to std).
// One CTA per (b, n); 128 threads x 4 channels.
// ---------------------------------------------------------------------------
__global__ __launch_bounds__(128) void ln_kernel(
    const float* __restrict__ x, const float* __restrict__ a2,
    const float* __restrict__ b2, float* __restrict__ out)
{
    const int bn = blockIdx.x;
    const int b = bn / N_, n = bn % N_;
    const int t = threadIdx.x;

    float v[4];
    #pragma unroll
    for (int i = 0; i < 4; i++) {
        int c = t + 128 * i;
        int h = c >> 6, d = c & 63;
        v[i] = g_o[((b * H_ + h) * N_ + n) * DK_ + d];
    }
    float s  = v[0] + v[1] + v[2] + v[3];
    float ss = v[0]*v[0] + v[1]*v[1] + v[2]*v[2] + v[3]*v[3];

    __shared__ float rs[4], rss[4];
    #pragma unroll
    for (int off = 16; off; off >>= 1) {
        s  += __shfl_xor_sync(0xffffffffu, s, off);
        ss += __shfl_xor_sync(0xffffffffu, ss, off);
    }
    int wi = t >> 5, li = t & 31;
    if (li == 0) { rs[wi] = s; rss[wi] = ss; }
    __syncthreads();
    s  = rs[0] + rs[1] + rs[2] + rs[3];
    ss = rss[0] + rss[1] + rss[2] + rss[3];

    float mean = s * (1.f / 512.f);
    float var  = (ss - 512.f * mean * mean) * (1.f / 511.f);
    var = fmaxf(var, 0.f);
    float inv = 1.f / (sqrtf(var) + 1e-6f);

    #pragma unroll
    for (int i = 0; i < 4; i++) {
        int c = t + 128 * i;
        float res = x[(b * C_ + c) * N_ + n];
        out[bn * C_ + c] = a2[c] * (v[i] - mean) * inv + b2[c] + res;
    }
}

// ---------------------------------------------------------------------------
extern "C" void kernel_launch(void* const* d_in, const int* in_sizes, int n_in,
                              void* d_out, int out_size)
{
    const float* x  = (const float*)d_in[0];
    const float* Wq = (const float*)d_in[1];
    const float* bq = (const float*)d_in[2];
    const float* Wk = (const float*)d_in[3];
    const float* bk = (const float*)d_in[4];
    const float* Wv = (const float*)d_in[5];
    const float* bv = (const float*)d_in[6];
    const float* a2 = (const float*)d_in[7];
    const float* b2 = (const float*)d_in[8];
    float* out = (float*)d_out;

    dim3 g1(24, 32, 2);
    qkv_kernel<<<g1, 256>>>(x, Wq, bq, Wk, bk, Wv, bv);

    const int smem_bytes = (QT * N_ + QT * DK_ + KC * VPAD) * 4;
    cudaFuncSetAttribute(attn_kernel, cudaFuncAttributeMaxDynamicSharedMemorySize,
                         smem_bytes);
    dim3 g2(N_ / QT, BH_);
    attn_kernel<<<g2, 512, smem_bytes>>>();

    ln_kernel<<<B_ * N_, 128>>>(x, a2, b2, out);
}

// round 4
// speedup vs baseline: 2.3932x; 2.3932x over previous
#include <cuda_runtime.h>
#include <cuda_bf16.h>
#include <cstdint>

#define B_  2
#define C_  512
#define N_  2048
#define H_  8
#define DK_ 64
#define BH_ (B_*H_)

__device__ float g_q[BH_*N_*DK_];
__device__ float g_k[BH_*N_*DK_];
__device__ float g_v[BH_*N_*DK_];
__device__ float g_o[BH_*N_*DK_];
__device__ __nv_bfloat16 g_vthi[BH_*DK_*N_];
__device__ __nv_bfloat16 g_vtlo[BH_*DK_*N_];
__device__ float g_e[(size_t)BH_*N_*N_];   // 268MB E/P scratch

// ---- warp MMA m16n8k16 row.col f32.bf16.bf16.f32 ----
__device__ __forceinline__ void mma16816(float* d, const uint32_t* a, const uint32_t* b) {
    asm volatile(
        "mma.sync.aligned.m16n8k16.row.col.f32.bf16.bf16.f32 "
        "{%0,%1,%2,%3}, {%4,%5,%6,%7}, {%8,%9}, {%0,%1,%2,%3};"
        : "+f"(d[0]), "+f"(d[1]), "+f"(d[2]), "+f"(d[3])
        : "r"(a[0]), "r"(a[1]), "r"(a[2]), "r"(a[3]), "r"(b[0]), "r"(b[1]));
}
__device__ __forceinline__ void split2(float x, float y, uint32_t& h, uint32_t& l) {
    __nv_bfloat162 hh, ll;
    hh.x = __float2bfloat16(x); ll.x = __float2bfloat16(x - __bfloat162float(hh.x));
    hh.y = __float2bfloat16(y); ll.y = __float2bfloat16(y - __bfloat162float(hh.y));
    h = *(uint32_t*)&hh; l = *(uint32_t*)&ll;
}
// A fragment (row-major [m][k], row stride sB bytes), 16x16 tile at row r0, k-byte-offset kb
__device__ __forceinline__ void lda(uint32_t* f, const char* base, int sB, int r0, int kb, int g, int tig) {
    const char* p = base + (r0 + g) * sB + kb + tig * 4;
    f[0] = *(const uint32_t*)p;
    f[1] = *(const uint32_t*)(p + 8 * sB);
    f[2] = *(const uint32_t*)(p + 16);
    f[3] = *(const uint32_t*)(p + 8 * sB + 16);
}
// B fragment (col-major stored [n][k], row stride sB bytes), 8(n)x16(k) tile
__device__ __forceinline__ void ldb(uint32_t* f, const char* base, int sB, int n0, int kb, int g, int tig) {
    const char* p = base + (n0 + g) * sB + kb + tig * 4;
    f[0] = *(const uint32_t*)p;
    f[1] = *(const uint32_t*)(p + 16);
}

// ---------------- Kernel 1: QKV via mma.sync ----------------
// grid (12 otiles*128, 16 ntiles*128, 2 b), 256 thr (8 warps, 2n x 4o).
__global__ __launch_bounds__(256, 1) void qkv_kernel(
    const float* __restrict__ x,
    const float* __restrict__ Wq, const float* __restrict__ bq,
    const float* __restrict__ Wk, const float* __restrict__ bk,
    const float* __restrict__ Wv, const float* __restrict__ bv)
{
    extern __shared__ char sm[];
    char* AHI = sm;            // [128 n][36 bf16] (72B rows)
    char* ALO = sm + 9216;
    char* BHI = sm + 18432;    // [128 o][36]
    char* BLO = sm + 27648;

    const int tid = threadIdx.x, w = tid >> 5, lane = tid & 31;
    const int g = lane >> 2, tig = lane & 3;
    const int o0 = blockIdx.x * 128, n0 = blockIdx.y * 128, b = blockIdx.z;
    const int mat = o0 >> 9, orow0 = o0 & 511;
    const float* W    = (mat == 0) ? Wq : (mat == 1) ? Wk : Wv;
    const float* bias = (mat == 0) ? bq : (mat == 1) ? bk : bv;
    float*       dst  = (mat == 0) ? g_q : (mat == 1) ? g_k : g_v;
    const int wm = (w >> 2) * 64, wn = (w & 3) * 32;

    float acc[4][4][4];
    #pragma unroll
    for (int i = 0; i < 4; i++)
        #pragma unroll
        for (int j = 0; j < 4; j++)
            #pragma unroll
            for (int r = 0; r < 4; r++) acc[i][j][r] = 0.f;

    for (int kc = 0; kc < 16; kc++) {
        const int c0 = kc * 32;
        __syncthreads();
        // x^T tile [128 n][32 c]: pairs along c
        for (int i = tid; i < 2048; i += 256) {
            int nn = i & 127, cp = i >> 7;
            float v0 = x[(b * C_ + c0 + 2 * cp)     * N_ + n0 + nn];
            float v1 = x[(b * C_ + c0 + 2 * cp + 1) * N_ + n0 + nn];
            uint32_t h, l; split2(v0, v1, h, l);
            *(uint32_t*)(AHI + nn * 72 + cp * 4) = h;
            *(uint32_t*)(ALO + nn * 72 + cp * 4) = l;
        }
        // W tile [128 o][32 c]
        for (int i = tid; i < 2048; i += 256) {
            int oo = i >> 4, cp = i & 15;
            float2 v = *(const float2*)(W + (orow0 + oo) * C_ + c0 + 2 * cp);
            uint32_t h, l; split2(v.x, v.y, h, l);
            *(uint32_t*)(BHI + oo * 72 + cp * 4) = h;
            *(uint32_t*)(BLO + oo * 72 + cp * 4) = l;
        }
        __syncthreads();

        #pragma unroll
        for (int ks = 0; ks < 2; ks++) {
            uint32_t ah[4][4], al[4][4], bh[4][2], bl[4][2];
            #pragma unroll
            for (int ms = 0; ms < 4; ms++) {
                lda(ah[ms], AHI, 72, wm + ms * 16, ks * 32, g, tig);
                lda(al[ms], ALO, 72, wm + ms * 16, ks * 32, g, tig);
            }
            #pragma unroll
            for (int ns = 0; ns < 4; ns++) {
                ldb(bh[ns], BHI, 72, wn + ns * 8, ks * 32, g, tig);
                ldb(bl[ns], BLO, 72, wn + ns * 8, ks * 32, g, tig);
            }
            #pragma unroll
            for (int ms = 0; ms < 4; ms++)
                #pragma unroll
                for (int ns = 0; ns < 4; ns++) {
                    mma16816(acc[ms][ns], ah[ms], bh[ns]);
                    mma16816(acc[ms][ns], ah[ms], bl[ns]);
                    mma16816(acc[ms][ns], al[ms], bh[ns]);
                }
        }
    }

    #pragma unroll
    for (int ms = 0; ms < 4; ms++)
        #pragma unroll
        for (int ns = 0; ns < 4; ns++) {
            int col = orow0 + wn + ns * 8 + tig * 2;
            int h = col >> 6, d = col & 63;
            float b0 = bias[col], b1 = bias[col + 1];
            int n = n0 + wm + ms * 16 + g;
            float* p0 = dst + (((size_t)(b * H_ + h) * N_ + n) * DK_ + d);
            float* p1 = dst + (((size_t)(b * H_ + h) * N_ + n + 8) * DK_ + d);
            *(float2*)p0 = make_float2(acc[ms][ns][0] + b0, acc[ms][ns][1] + b1);
            *(float2*)p1 = make_float2(acc[ms][ns][2] + b0, acc[ms][ns][3] + b1);
        }
}

// ---------------- Kernel 2: E = QK^T/16 via mma.sync ----------------
// grid (16 qtiles, 16 bh), 256 thr (8 warps, 2m x 4n). CTA: 128q x 2048k, K=64.
__global__ __launch_bounds__(256, 1) void energy_kernel()
{
    extern __shared__ char sm[];
    char* QHI = sm;            // [128][72 bf16] (144B rows)
    char* QLO = sm + 18432;
    char* KHI = sm + 36864;
    char* KLO = sm + 55296;

    const int tid = threadIdx.x, w = tid >> 5, lane = tid & 31;
    const int g = lane >> 2, tig = lane & 3;
    const int q0 = blockIdx.x * 128, bh = blockIdx.y;
    const int wm = (w >> 2) * 64, wn = (w & 3) * 32;

    const float* qp = g_q + ((size_t)bh * N_ + q0) * DK_;
    for (int i = tid; i < 4096; i += 256) {
        int r = i >> 5, c2 = i & 31;
        float2 v = *(const float2*)(qp + r * 64 + c2 * 2);
        uint32_t h, l; split2(v.x, v.y, h, l);
        *(uint32_t*)(QHI + r * 144 + c2 * 4) = h;
        *(uint32_t*)(QLO + r * 144 + c2 * 4) = l;
    }
    const float* kp = g_k + (size_t)bh * N_ * DK_;
    float* ep = g_e + ((size_t)bh * N_ + q0) * N_;

    for (int kc = 0; kc < 16; kc++) {
        __syncthreads();
        for (int i = tid; i < 4096; i += 256) {
            int r = i >> 5, c2 = i & 31;
            float2 v = *(const float2*)(kp + (size_t)(kc * 128 + r) * 64 + c2 * 2);
            uint32_t h, l; split2(v.x, v.y, h, l);
            *(uint32_t*)(KHI + r * 144 + c2 * 4) = h;
            *(uint32_t*)(KLO + r * 144 + c2 * 4) = l;
        }
        __syncthreads();

        float acc[4][4][4];
        #pragma unroll
        for (int i = 0; i < 4; i++)
            #pragma unroll
            for (int j = 0; j < 4; j++)
                #pragma unroll
                for (int r = 0; r < 4; r++) acc[i][j][r] = 0.f;

        #pragma unroll
        for (int ks = 0; ks < 4; ks++) {
            uint32_t ah[4][4], al[4][4], bh2[4][2], bl2[4][2];
            #pragma unroll
            for (int ms = 0; ms < 4; ms++) {
                lda(ah[ms], QHI, 144, wm + ms * 16, ks * 32, g, tig);
                lda(al[ms], QLO, 144, wm + ms * 16, ks * 32, g, tig);
            }
            #pragma unroll
            for (int ns = 0; ns < 4; ns++) {
                ldb(bh2[ns], KHI, 144, wn + ns * 8, ks * 32, g, tig);
                ldb(bl2[ns], KLO, 144, wn + ns * 8, ks * 32, g, tig);
            }
            #pragma unroll
            for (int ms = 0; ms < 4; ms++)
                #pragma unroll
                for (int ns = 0; ns < 4; ns++) {
                    mma16816(acc[ms][ns], ah[ms], bh2[ns]);
                    mma16816(acc[ms][ns], ah[ms], bl2[ns]);
                    mma16816(acc[ms][ns], al[ms], bh2[ns]);
                }
        }
        const float s = 0.0625f;
        #pragma unroll
        for (int ms = 0; ms < 4; ms++)
            #pragma unroll
            for (int ns = 0; ns < 4; ns++) {
                int row = wm + ms * 16 + g;
                int col = kc * 128 + wn + ns * 8 + tig * 2;
                *(float2*)(ep + (size_t)row * N_ + col) =
                    make_float2(acc[ms][ns][0] * s, acc[ms][ns][1] * s);
                *(float2*)(ep + (size_t)(row + 8) * N_ + col) =
                    make_float2(acc[ms][ns][2] * s, acc[ms][ns][3] * s);
            }
    }
}

// ---------------- Kernel 3: 1.5-entmax in place over g_e ----------------
// warp per row: 14 bisections to isolate support, then exact quadratic tau.
__global__ __launch_bounds__(256) void entmax_kernel()
{
    const int wid = threadIdx.x >> 5, lane = threadIdx.x & 31;
    float* rp = g_e + ((size_t)blockIdx.x * 8 + wid) * N_;

    float z[64];
    #pragma unroll
    for (int b = 0; b < 16; b++) {
        float4 v = *(const float4*)(rp + b * 128 + lane * 4);
        z[4*b] = v.x; z[4*b+1] = v.y; z[4*b+2] = v.z; z[4*b+3] = v.w;
    }
    float m = z[0];
    #pragma unroll
    for (int j = 1; j < 64; j++) m = fmaxf(m, z[j]);
    #pragma unroll
    for (int o = 16; o; o >>= 1) m = fmaxf(m, __shfl_xor_sync(0xffffffffu, m, o));
    #pragma unroll
    for (int j = 0; j < 64; j++) z[j] -= m;

    float lo = -1.f, hi = 0.f;
    for (int it = 0; it < 14; it++) {
        float mid = 0.5f * (lo + hi), s = 0.f;
        #pragma unroll
        for (int j = 0; j < 64; j++) {
            float t = fmaxf(z[j] - mid, 0.f);
            s = fmaf(t, t, s);
        }
        #pragma unroll
        for (int o = 16; o; o >>= 1) s += __shfl_xor_sync(0xffffffffu, s, o);
        if (s >= 1.f) lo = mid; else hi = mid;
    }
    // exact tau over support {z > lo}
    float c1 = 0.f, c2 = 0.f, cnt = 0.f;
    #pragma unroll
    for (int j = 0; j < 64; j++) {
        if (z[j] > lo) { c1 += z[j]; c2 = fmaf(z[j], z[j], c2); cnt += 1.f; }
    }
    #pragma unroll
    for (int o = 16; o; o >>= 1) {
        c1 += __shfl_xor_sync(0xffffffffu, c1, o);
        c2 += __shfl_xor_sync(0xffffffffu, c2, o);
        cnt += __shfl_xor_sync(0xffffffffu, cnt, o);
    }
    float disc = fmaxf(fmaf(c1, c1, -cnt * (c2 - 1.f)), 0.f);
    float tau = (c1 - sqrtf(disc)) / cnt;
    tau = fminf(fmaxf(tau, lo), hi);

    #pragma unroll
    for (int b = 0; b < 16; b++) {
        float t0 = fmaxf(z[4*b]   - tau, 0.f);
        float t1 = fmaxf(z[4*b+1] - tau, 0.f);
        float t2 = fmaxf(z[4*b+2] - tau, 0.f);
        float t3 = fmaxf(z[4*b+3] - tau, 0.f);
        *(float4*)(rp + b * 128 + lane * 4) = make_float4(t0*t0, t1*t1, t2*t2, t3*t3);
    }
}

// ---------------- Kernel 4: V transpose -> bf16 hi/lo [bh][d][k] ----------------
__global__ __launch_bounds__(256) void vt_kernel()
{
    __shared__ float t[64][65];
    const int tid = threadIdx.x, k0 = blockIdx.x * 64, bh = blockIdx.y;
    for (int i = tid; i < 4096; i += 256) {
        int k = i >> 6, d = i & 63;
        t[k][d] = g_v[((size_t)bh * N_ + k0 + k) * DK_ + d];
    }
    __syncthreads();
    for (int i = tid; i < 4096; i += 256) {
        int d = i >> 6, kk = i & 63;
        float v = t[kk][d];
        __nv_bfloat16 h = __float2bfloat16(v);
        __nv_bfloat16 l = __float2bfloat16(v - __bfloat162float(h));
        size_t o = ((size_t)bh * DK_ + d) * N_ + k0 + kk;
        g_vthi[o] = h; g_vtlo[o] = l;
    }
}

// ---------------- Kernel 5: O = P V via mma.sync ----------------
// grid (16 qtiles, 16 bh), 256 thr (8 warps, 2m x 4n). CTA: 128q x 64d, K=2048.
__global__ __launch_bounds__(256, 1) void pv_kernel()
{
    extern __shared__ char sm[];
    char* PHI = sm;            // [128 q][136 bf16] (272B rows)
    char* PLO = sm + 34816;
    char* VHI = sm + 69632;    // [64 d][136]
    char* VLO = sm + 87040;

    const int tid = threadIdx.x, w = tid >> 5, lane = tid & 31;
    const int g = lane >> 2, tig = lane & 3;
    const int q0 = blockIdx.x * 128, bh = blockIdx.y;
    const int wm = (w >> 2) * 64, wn = (w & 3) * 16;

    const float* pp = g_e + ((size_t)bh * N_ + q0) * N_;
    const __nv_bfloat16* vh = g_vthi + (size_t)bh * DK_ * N_;
    const __nv_bfloat16* vl = g_vtlo + (size_t)bh * DK_ * N_;

    float acc[4][2][4];
    #pragma unroll
    for (int i = 0; i < 4; i++)
        #pragma unroll
        for (int j = 0; j < 2; j++)
            #pragma unroll
            for (int r = 0; r < 4; r++) acc[i][j][r] = 0.f;

    for (int kc = 0; kc < 16; kc++) {
        __syncthreads();
        for (int i = tid; i < 8192; i += 256) {   // P chunk [128][128]
            int r = i >> 6, c2 = i & 63;
            float2 v = *(const float2*)(pp + (size_t)r * N_ + kc * 128 + c2 * 2);
            uint32_t h, l; split2(v.x, v.y, h, l);
            *(uint32_t*)(PHI + r * 272 + c2 * 4) = h;
            *(uint32_t*)(PLO + r * 272 + c2 * 4) = l;
        }
        for (int i = tid; i < 4096; i += 256) {   // VT chunk [64][128]
            int d = i >> 6, k2 = i & 63;
            size_t o = (size_t)d * N_ + kc * 128 + k2 * 2;
            *(uint32_t*)(VHI + d * 272 + k2 * 4) = *(const uint32_t*)(vh + o);
            *(uint32_t*)(VLO + d * 272 + k2 * 4) = *(const uint32_t*)(vl + o);
        }
        __syncthreads();

        #pragma unroll
        for (int ks = 0; ks < 8; ks++) {
            uint32_t ah[4][4], al[4][4], bh2[2][2], bl2[2][2];
            #pragma unroll
            for (int ms = 0; ms < 4; ms++) {
                lda(ah[ms], PHI, 272, wm + ms * 16, ks * 32, g, tig);
                lda(al[ms], PLO, 272, wm + ms * 16, ks * 32, g, tig);
            }
            #pragma unroll
            for (int ns = 0; ns < 2; ns++) {
                ldb(bh2[ns], VHI, 272, wn + ns * 8, ks * 32, g, tig);
                ldb(bl2[ns], VLO, 272, wn + ns * 8, ks * 32, g, tig);
            }
            #pragma unroll
            for (int ms = 0; ms < 4; ms++)
                #pragma unroll
                for (int ns = 0; ns < 2; ns++) {
                    mma16816(acc[ms][ns], ah[ms], bh2[ns]);
                    mma16816(acc[ms][ns], ah[ms], bl2[ns]);
                    mma16816(acc[ms][ns], al[ms], bh2[ns]);
                }
        }
    }

    #pragma unroll
    for (int ms = 0; ms < 4; ms++)
        #pragma unroll
        for (int ns = 0; ns < 2; ns++) {
            int row = q0 + wm + ms * 16 + g;
            int col = wn + ns * 8 + tig * 2;
            float* p0 = g_o + ((size_t)bh * N_ + row) * DK_ + col;
            float* p1 = g_o + ((size_t)bh * N_ + row + 8) * DK_ + col;
            *(float2*)p0 = make_float2(acc[ms][ns][0], acc[ms][ns][1]);
            *(float2*)p1 = make_float2(acc[ms][ns][2], acc[ms][ns][3]);
        }
}

// ---------------- Kernel 6: residual + LayerNorm ----------------
__global__ __launch_bounds__(128) void ln_kernel(
    const float* __restrict__ x, const float* __restrict__ a2,
    const float* __restrict__ b2, float* __restrict__ out)
{
    const int bn = blockIdx.x, b = bn / N_, n = bn % N_, t = threadIdx.x;
    float v[4];
    #pragma unroll
    for (int i = 0; i < 4; i++) {
        int c = t + 128 * i, h = c >> 6, d = c & 63;
        v[i] = g_o[((size_t)(b * H_ + h) * N_ + n) * DK_ + d];
    }
    float s  = v[0] + v[1] + v[2] + v[3];
    float ss = v[0]*v[0] + v[1]*v[1] + v[2]*v[2] + v[3]*v[3];
    __shared__ float rs[4], rss[4];
    #pragma unroll
    for (int o = 16; o; o >>= 1) {
        s  += __shfl_xor_sync(0xffffffffu, s, o);
        ss += __shfl_xor_sync(0xffffffffu, ss, o);
    }
    int wi = t >> 5, li = t & 31;
    if (li == 0) { rs[wi] = s; rss[wi] = ss; }
    __syncthreads();
    s = rs[0] + rs[1] + rs[2] + rs[3];
    ss = rss[0] + rss[1] + rss[2] + rss[3];
    float mean = s * (1.f / 512.f);
    float var  = fmaxf((ss - 512.f * mean * mean) * (1.f / 511.f), 0.f);
    float inv  = 1.f / (sqrtf(var) + 1e-6f);
    #pragma unroll
    for (int i = 0; i < 4; i++) {
        int c = t + 128 * i;
        out[bn * C_ + c] = a2[c] * (v[i] - mean) * inv + b2[c] + x[(b * C_ + c) * N_ + n];
    }
}

// ---------------------------------------------------------------------------
extern "C" void kernel_launch(void* const* d_in, const int* in_sizes, int n_in,
                              void* d_out, int out_size)
{
    const float* x  = (const float*)d_in[0];
    const float* Wq = (const float*)d_in[1];
    const float* bq = (const float*)d_in[2];
    const float* Wk = (const float*)d_in[3];
    const float* bk = (const float*)d_in[4];
    const float* Wv = (const float*)d_in[5];
    const float* bv = (const float*)d_in[6];
    const float* a2 = (const float*)d_in[7];
    const float* b2 = (const float*)d_in[8];
    float* out = (float*)d_out;

    static int configured = 0;
    if (!configured) {
        cudaFuncSetAttribute(qkv_kernel, cudaFuncAttributeMaxDynamicSharedMemorySize, 36864);
        cudaFuncSetAttribute(energy_kernel, cudaFuncAttributeMaxDynamicSharedMemorySize, 73728);
        cudaFuncSetAttribute(pv_kernel, cudaFuncAttributeMaxDynamicSharedMemorySize, 104448);
        configured = 1;
    }

    qkv_kernel<<<dim3(12, 16, 2), 256, 36864>>>(x, Wq, bq, Wk, bk, Wv, bv);
    energy_kernel<<<dim3(16, 16), 256, 73728>>>();
    entmax_kernel<<<BH_ * N_ / 8, 256>>>();
    vt_kernel<<<dim3(32, 16), 256>>>();
    pv_kernel<<<dim3(16, 16), 256, 104448>>>();
    ln_kernel<<<B_ * N_, 128>>>(x, a2, b2, out);
}